// round 4
// baseline (speedup 1.0000x reference)
#include <cuda_runtime.h>
#include <cuda_fp16.h>

#define IC 1152
#define BB 256
#define NU 10
#define US 16
#define DU 160   /* NU*US */
#define IU 8

// Scratch (allocation-free rule: __device__ globals)
__device__ __align__(16) __half g_Uh[(size_t)IC * BB * DU];  // 94.4 MB fp16 u_hat, layout [c][b][du]
__device__ __align__(16) __half g_Vh[BB * DU];               // v in fp16 for agree pass
__device__ float g_Bij[IC * NU];                             // routing logits

// ---------------------------------------------------------------------------
// k_build: u_hat[c][b][du] = sum_i W[c,du,i] * x[b,i,c], stored fp16.
// grid 1152 (c), block 320 (du = t%160, b-parity = t/160)
// ---------------------------------------------------------------------------
__global__ void __launch_bounds__(320) k_build(const float* __restrict__ x,
                                               const float* __restrict__ W) {
    __shared__ float Wt[IU][DU];     // transposed W[c] for conflict-free LDS
    __shared__ float xs[BB][IU];     // x[:, :, c]
    const int c = blockIdx.x;
    const int t = threadIdx.x;

    // zero routing logits (must happen every launch; done before any reader kernel)
    if (blockIdx.x == 0) {
        for (int i = t; i < IC * NU; i += 320) g_Bij[i] = 0.0f;
    }

    const float* Wc = W + c * (DU * IU);
    for (int idx = t; idx < DU * IU; idx += 320) {
        const int du = idx >> 3, i = idx & 7;
        Wt[i][du] = Wc[idx];
    }
    for (int idx = t; idx < BB * IU; idx += 320) {
        const int b = idx >> 3, i = idx & 7;
        xs[b][i] = x[(b * IU + i) * IC + c];
    }
    __syncthreads();

    const int du = t % DU;
    const int hp = t / DU;  // 0 or 1
    const float w0 = Wt[0][du], w1 = Wt[1][du], w2 = Wt[2][du], w3 = Wt[3][du];
    const float w4 = Wt[4][du], w5 = Wt[5][du], w6 = Wt[6][du], w7 = Wt[7][du];
    __half* out = g_Uh + (size_t)c * (BB * DU) + du;

#pragma unroll 4
    for (int b = hp; b < BB; b += 2) {
        const float4 xa = *reinterpret_cast<const float4*>(&xs[b][0]);
        const float4 xb = *reinterpret_cast<const float4*>(&xs[b][4]);
        float acc = w0 * xa.x + w1 * xa.y + w2 * xa.z + w3 * xa.w
                  + w4 * xb.x + w5 * xb.y + w6 * xb.z + w7 * xb.w;
        out[b * DU] = __float2half_rn(acc);
    }
}

// ---------------------------------------------------------------------------
// k_s: fused (softmax over channels) + s_j reduce + squash -> v
// grid 256 (b), block 320: dug = t%20 (8 du each, within one d), cp = t/20 (16-way c split)
// ---------------------------------------------------------------------------
__global__ void __launch_bounds__(320) k_s(float* __restrict__ vout) {
    __shared__ float pool[IC * NU];          // 46 KB: exp(b_ij - max), later reused as reduce buf
    __shared__ float pm[16][NU], psum[16][NU];
    __shared__ float cmax[NU], cinv[NU];
    __shared__ float svec[DU];
    __shared__ float msq[US];

    const int t = threadIdx.x;
    const int b = blockIdx.x;

    // --- softmax over in_channels (axis 0) of b_ij [IC, NU] ---
    for (int i = t; i < IC * NU; i += 320) pool[i] = g_Bij[i];
    __syncthreads();
    if (t < 160) {
        const int d = t % NU, seg = t / NU;
        float m = -1e30f;
        for (int c = seg; c < IC; c += 16) m = fmaxf(m, pool[c * NU + d]);
        pm[seg][d] = m;
    }
    __syncthreads();
    if (t < NU) {
        float m = pm[0][t];
#pragma unroll
        for (int s = 1; s < 16; s++) m = fmaxf(m, pm[s][t]);
        cmax[t] = m;
    }
    __syncthreads();
    for (int i = t; i < IC * NU; i += 320) pool[i] = __expf(pool[i] - cmax[i % NU]);
    __syncthreads();
    if (t < 160) {
        const int d = t % NU, seg = t / NU;
        float s = 0.0f;
        for (int c = seg; c < IC; c += 16) s += pool[c * NU + d];
        psum[seg][d] = s;
    }
    __syncthreads();
    if (t < NU) {
        float s = 0.0f;
#pragma unroll
        for (int k = 0; k < 16; k++) s += psum[k][t];
        cinv[t] = 1.0f / s;
    }
    __syncthreads();

    // --- s_j[b,du] = sum_c c_ij[c,d] * u_hat[c][b][du] ---
    const int dug = t % 20, cp = t / 20;
    const int du0 = dug * 8;
    const int d = du0 / US;           // each 8-du group lies in one d
    const float inv = cinv[d];
    float acc[8];
#pragma unroll
    for (int j = 0; j < 8; j++) acc[j] = 0.0f;

    const __half* Ub = g_Uh + b * DU + du0;
#pragma unroll 4
    for (int k = 0; k < 72; k++) {
        const int c = cp + (k << 4);
        const uint4 raw = *reinterpret_cast<const uint4*>(Ub + (size_t)c * (BB * DU));
        const float w = pool[c * NU + d] * inv;
        const __half2* h = reinterpret_cast<const __half2*>(&raw);
#pragma unroll
        for (int j = 0; j < 4; j++) {
            const float2 f = __half22float2(h[j]);
            acc[2 * j]     += w * f.x;
            acc[2 * j + 1] += w * f.y;
        }
    }
    __syncthreads();  // pool (exp values) fully consumed; reuse as reduce buffer
    float* red = pool;
#pragma unroll
    for (int j = 0; j < 8; j++) red[cp * DU + du0 + j] = acc[j];
    __syncthreads();
    if (t < DU) {
        float s = 0.0f;
#pragma unroll
        for (int p = 0; p < 16; p++) s += red[p * DU + t];
        svec[t] = s;
    }
    __syncthreads();

    // --- squash: norm over num_units axis per (b, u) ---
    if (t < US) {
        float m = 0.0f;
#pragma unroll
        for (int dd = 0; dd < NU; dd++) {
            const float v = svec[dd * US + t];
            m += v * v;
        }
        msq[t] = m;
    }
    __syncthreads();
    if (t < DU) {
        const float m = msq[t % US];
        const float scale = sqrtf(m) / (1.0f + m);
        const float v = svec[t] * scale;
        vout[b * DU + t] = v;
        g_Vh[b * DU + t] = __float2half_rn(v);
    }
}

// ---------------------------------------------------------------------------
// k_agree: b_ij[c,d] += (1/B) sum_{b,u} u_hat[c][b][d*16+u] * v[b][d*16+u]
// grid 144 (8 c's per block), block 320: dug = t%20, bp = t/20
// ---------------------------------------------------------------------------
__global__ void __launch_bounds__(320) k_agree() {
    __shared__ float sacc[320];
    const int t = threadIdx.x;
    const int dug = t % 20, bp = t / 20;   // bp in [0,16)
    const int du0 = dug * 8;
    const int c0 = blockIdx.x * 8;

    for (int ci = 0; ci < 8; ci++) {
        const int c = c0 + ci;
        const __half* Ub = g_Uh + (size_t)c * (BB * DU) + du0;
        float acc = 0.0f;
#pragma unroll 4
        for (int bs = 0; bs < 16; bs++) {
            const int b = bs * 16 + bp;
            const uint4 ur = *reinterpret_cast<const uint4*>(Ub + b * DU);
            const uint4 vr = *reinterpret_cast<const uint4*>(g_Vh + b * DU + du0);
            const __half2* up = reinterpret_cast<const __half2*>(&ur);
            const __half2* vp = reinterpret_cast<const __half2*>(&vr);
#pragma unroll
            for (int j = 0; j < 4; j++) {
                const float2 uf = __half22float2(up[j]);
                const float2 vf = __half22float2(vp[j]);
                acc += uf.x * vf.x + uf.y * vf.y;
            }
        }
        sacc[t] = acc;
        __syncthreads();
        if (t < NU) {
            float s = 0.0f;
#pragma unroll
            for (int p = 0; p < 16; p++)
                s += sacc[p * 20 + 2 * t] + sacc[p * 20 + 2 * t + 1];
            g_Bij[c * NU + t] += s * (1.0f / 256.0f);
        }
        __syncthreads();
    }
}

// ---------------------------------------------------------------------------
extern "C" void kernel_launch(void* const* d_in, const int* in_sizes, int n_in,
                              void* d_out, int out_size) {
    const float* x;
    const float* W;
    // identify by element count: x = 256*8*1152 = 2359296, W = 1152*10*16*8 = 1474560
    if (in_sizes[0] == BB * IU * IC) {
        x = (const float*)d_in[0];
        W = (const float*)d_in[1];
    } else {
        W = (const float*)d_in[0];
        x = (const float*)d_in[1];
    }
    float* out = (float*)d_out;

    k_build<<<IC, 320>>>(x, W);
    for (int it = 0; it < 3; it++) {
        k_s<<<BB, 320>>>(out);
        if (it < 2) k_agree<<<144, 320>>>();
    }
}